// round 5
// baseline (speedup 1.0000x reference)
#include <cuda_runtime.h>

typedef unsigned long long ull;

#define BN 16
#define TILE 64

__device__ float g_q[25000 * 224];
__device__ float g_k[25000 * 224];
__device__ float g_v[25000 * 224];
__device__ float g_w2p[224 * 224];   // [k][c] = concat(W2r,W2s)[k][c]
__device__ float g_wqT[7168];        // [h][j*32+i]
__device__ float g_wkT[7168];
__device__ float g_wvT[12544];       // [h][j*56+i]

__device__ __forceinline__ float silu_f(float x) { return x / (1.0f + __expf(-x)); }

__device__ __forceinline__ ull fpack2(float lo, float hi) {
    ull u; asm("mov.b64 %0,{%1,%2};" : "=l"(u) : "f"(lo), "f"(hi)); return u;
}
__device__ __forceinline__ void funpack2(ull u, float& lo, float& hi) {
    asm("mov.b64 {%0,%1},%2;" : "=f"(lo), "=f"(hi) : "l"(u));
}
__device__ __forceinline__ void ffma2(ull& d, ull a, ull b) {
    asm("fma.rn.f32x2 %0, %1, %2, %0;" : "+l"(d) : "l"(a), "l"(b));
}

// ---------------------------------------------------------------------------
// prep: zero outputs, concat W2, transpose node weights
__global__ void k_prep(const float* __restrict__ W2r, const float* __restrict__ W2s,
                       const float* __restrict__ Wq, const float* __restrict__ Wk,
                       const float* __restrict__ Wv,
                       float* __restrict__ outx, float* __restrict__ outev, int N)
{
    int gid = blockIdx.x * blockDim.x + threadIdx.x;
    int st = gridDim.x * blockDim.x;
    int nx = N * 224, nz = N * 239;
    for (int i = gid; i < nz; i += st) {
        if (i < nx) outx[i] = 0.f; else outev[i - nx] = 0.f;
    }
    for (int i = gid; i < 224 * 224; i += st) {
        g_w2p[i] = (i < 112 * 224) ? W2r[i] : W2s[i - 112 * 224];
    }
    for (int i = gid; i < 7168; i += st) {
        int h = i >> 10, rem = i & 1023, jj = rem >> 5, ich = rem & 31;
        g_wqT[i] = Wq[h * 1024 + ich * 32 + jj];
        g_wkT[i] = Wk[h * 1024 + ich * 32 + jj];
    }
    for (int i = gid; i < 12544; i += st) {
        int h = i / 3136, rem = i - h * 3136, jj = rem / 56, ich = rem - jj * 56;
        g_wvT[i] = Wv[h * 3136 + ich * 56 + jj];
    }
}

// ---------------------------------------------------------------------------
// node kernel: q = silu(Wq x), k = silu(Wk x), v = Wv x
__global__ void __launch_bounds__(256, 3) k_node(const float* __restrict__ x, int N)
{
    __shared__ float xs[BN * 224];
    int tid = threadIdx.x;
    int nb0 = blockIdx.x * BN;
    int cnt = N - nb0; if (cnt > BN) cnt = BN; if (cnt < 0) cnt = 0;

    for (int idx = tid; idx < BN * 224; idx += 256) {
        int u = idx / 224, f = idx - u * 224;
        xs[idx] = (u < cnt) ? x[(nb0 + u) * 224 + f] : 0.0f;
    }
    __syncthreads();

    if (tid < 224) {
        int h = tid >> 5, iq = tid & 31;
        int hv = tid / 56, iv = tid - hv * 56;
        float aq[BN], ak[BN], av[BN];
#pragma unroll
        for (int u = 0; u < BN; u++) { aq[u] = 0.f; ak[u] = 0.f; av[u] = 0.f; }
#pragma unroll 4
        for (int j = 0; j < 32; j++) {
            float wq = g_wqT[h * 1024 + j * 32 + iq];
            float wk = g_wkT[h * 1024 + j * 32 + iq];
#pragma unroll
            for (int u = 0; u < BN; u++) {
                float xv = xs[u * 224 + h * 32 + j];
                aq[u] += wq * xv; ak[u] += wk * xv;
            }
        }
#pragma unroll 4
        for (int j = 0; j < 56; j++) {
            float wv = g_wvT[hv * 3136 + j * 56 + iv];
#pragma unroll
            for (int u = 0; u < BN; u++) av[u] += wv * xs[u * 224 + hv * 56 + j];
        }
        for (int u = 0; u < cnt; u++) {
            g_q[(nb0 + u) * 224 + tid] = silu_f(aq[u]);
            g_k[(nb0 + u) * 224 + tid] = silu_f(ak[u]);
            g_v[(nb0 + u) * 224 + tid] = av[u];
        }
    }
}

// ---------------------------------------------------------------------------
// edge kernel smem layout (floats), TILE=64, 256 threads, 3 blocks/SM
#define OFF_ACT  0          // 224 * 66 = 14784  (k-major, stride 66)
#define OFF_RBF  14784      // 64*32 = 2048   (phase-A scratch)
#define OFF_TMP  16832      // 64*15 = 960
#define OFF_L0   17792      // 64*3  = 192
#define OFF_ALPH 17984      // 64*7  = 448
#define OFF_CUT  18432      // 64
#define OFF_I    18496      // 64
#define OFF_J    18560      // 64
#define EDGE_SMEM_FLOATS 18624   // 74496 B

__global__ void __launch_bounds__(256, 3) k_edge(
    const float* __restrict__ ev, const float* __restrict__ rbf,
    const float* __restrict__ ylm, const float* __restrict__ cut,
    const int* __restrict__ idx_i, const int* __restrict__ idx_j,
    const float* __restrict__ W1r, const float* __restrict__ b1r,
    const float* __restrict__ b2r,
    const float* __restrict__ W1s, const float* __restrict__ b1s,
    const float* __restrict__ b2s,
    float* __restrict__ outx, float* __restrict__ outev, int P)
{
    extern __shared__ float sm[];
    int* sI = (int*)(sm + OFF_I);
    int* sJ = (int*)(sm + OFF_J);

    int tid = threadIdx.x, tx = tid & 31, ty = tid >> 5;
    int p0 = blockIdx.x * TILE;
    int vend = P - p0; if (vend > TILE) vend = TILE;

    for (int idx = tid; idx < TILE; idx += 256) {
        int p = p0 + idx; bool v = p < P;
        sI[idx] = v ? idx_i[p] : 0;
        sJ[idx] = v ? idx_j[p] : 0;
        sm[OFF_CUT + idx] = v ? cut[p] : 0.f;
    }
    __syncthreads();
    for (int idx = tid; idx < TILE * 32; idx += 256) {
        int e = idx >> 5, j = idx & 31; int p = p0 + e;
        sm[OFF_RBF + idx] = (p < P) ? rbf[p * 32 + j] * sm[OFF_CUT + e] : 0.f;
    }
    for (int idx = tid; idx < TILE * 15; idx += 256) {
        int e = idx / 15, o = idx - e * 15; int p = p0 + e;
        float d = 0.f;
        if (p < P) d = ev[sJ[e] * 15 + o] - ev[sI[e] * 15 + o];
        sm[OFF_TMP + idx] = d * d;
    }
    __syncthreads();
    for (int idx = tid; idx < TILE * 3; idx += 256) {
        int e = idx / 3, dg = idx - e * 3;
        int o0 = (dg == 0) ? 0 : ((dg == 1) ? 3 : 8);
        int o1 = (dg == 0) ? 3 : ((dg == 1) ? 8 : 15);
        float s = 0.f;
        for (int o = o0; o < o1; o++) s += sm[OFF_TMP + e * 15 + o];
        sm[OFF_L0 + idx] = s;
    }
    __syncthreads();

    // ---- Phase A: hidden acts, thread = channel a (0..223), 4 chunks of 16
    if (tid < 224) {
        int a = tid;
        bool isr = (a < 112);
        float b0 = isr ? b1r[a] : b1s[a - 112];
        float ws0 = 0, ws1 = 0, ws2 = 0;
        if (!isr) {
            ws0 = W1s[a - 112]; ws1 = W1s[112 + a - 112]; ws2 = W1s[224 + a - 112];
        }
        for (int ch = 0; ch < 4; ch++) {
            float acc[16];
#pragma unroll
            for (int e = 0; e < 16; e++) acc[e] = b0;
            if (isr) {
#pragma unroll
                for (int j4 = 0; j4 < 8; j4++) {
                    float w0 = W1r[(j4 * 4 + 0) * 112 + a];
                    float w1 = W1r[(j4 * 4 + 1) * 112 + a];
                    float w2v = W1r[(j4 * 4 + 2) * 112 + a];
                    float w3 = W1r[(j4 * 4 + 3) * 112 + a];
#pragma unroll
                    for (int e = 0; e < 16; e++) {
                        float4 r4 = *(const float4*)&sm[OFF_RBF + (ch * 16 + e) * 32 + j4 * 4];
                        acc[e] += r4.x * w0 + r4.y * w1 + r4.z * w2v + r4.w * w3;
                    }
                }
            } else {
#pragma unroll
                for (int e = 0; e < 16; e++) {
                    int ee = ch * 16 + e;
                    acc[e] += sm[OFF_L0 + ee * 3] * ws0 + sm[OFF_L0 + ee * 3 + 1] * ws1
                            + sm[OFF_L0 + ee * 3 + 2] * ws2;
                }
            }
#pragma unroll
            for (int e = 0; e < 16; e++)
                sm[OFF_ACT + a * 66 + ch * 16 + e] = silu_f(acc[e]);
        }
    }
    __syncthreads();

    // ---- Phase B: w = act @ W2cat + b2; weights via L1 (LDG), act via LDS
    // thread: 4 edge-pairs (warp ty -> edges [ty*8, ty*8+8)) x 7 channels
    ull acc2[4][7];
#pragma unroll
    for (int r = 0; r < 7; r++) {
        int c = tx + 32 * r;
        float b2 = b2r[c] + b2s[c];
        ull bb = fpack2(b2, b2);
#pragma unroll
        for (int ep = 0; ep < 4; ep++) acc2[ep][r] = bb;
    }

    {
        const float* wp = g_w2p + tx;
        const float* ab = &sm[OFF_ACT + ty * 8];
#pragma unroll 4
        for (int k = 0; k < 224; k++) {
            const float* wk = wp + k * 224;
            float w0 = __ldg(wk);
            float w1 = __ldg(wk + 32);
            float w2v = __ldg(wk + 64);
            float w3 = __ldg(wk + 96);
            float w4 = __ldg(wk + 128);
            float w5 = __ldg(wk + 160);
            float w6 = __ldg(wk + 192);
            const ull* ap = (const ull*)(ab + k * 66);
            ull a0 = ap[0], a1 = ap[1], a2 = ap[2], a3 = ap[3];
            ull ww;
            ww = fpack2(w0, w0);
            ffma2(acc2[0][0], a0, ww); ffma2(acc2[1][0], a1, ww);
            ffma2(acc2[2][0], a2, ww); ffma2(acc2[3][0], a3, ww);
            ww = fpack2(w1, w1);
            ffma2(acc2[0][1], a0, ww); ffma2(acc2[1][1], a1, ww);
            ffma2(acc2[2][1], a2, ww); ffma2(acc2[3][1], a3, ww);
            ww = fpack2(w2v, w2v);
            ffma2(acc2[0][2], a0, ww); ffma2(acc2[1][2], a1, ww);
            ffma2(acc2[2][2], a2, ww); ffma2(acc2[3][2], a3, ww);
            ww = fpack2(w3, w3);
            ffma2(acc2[0][3], a0, ww); ffma2(acc2[1][3], a1, ww);
            ffma2(acc2[2][3], a2, ww); ffma2(acc2[3][3], a3, ww);
            ww = fpack2(w4, w4);
            ffma2(acc2[0][4], a0, ww); ffma2(acc2[1][4], a1, ww);
            ffma2(acc2[2][4], a2, ww); ffma2(acc2[3][4], a3, ww);
            ww = fpack2(w5, w5);
            ffma2(acc2[0][5], a0, ww); ffma2(acc2[1][5], a1, ww);
            ffma2(acc2[2][5], a2, ww); ffma2(acc2[3][5], a3, ww);
            ww = fpack2(w6, w6);
            ffma2(acc2[0][6], a0, ww); ffma2(acc2[1][6], a1, ww);
            ffma2(acc2[2][6], a2, ww); ffma2(acc2[3][6], a3, ww);
        }
    }

    // ---- Epilogue: alpha[e][r] = cut * sum_c w*q_i*k_j
#pragma unroll
    for (int ep = 0; ep < 4; ep++) {
        int e0 = ty * 8 + 2 * ep, e1 = e0 + 1;
        int i0 = sI[e0], j0 = sJ[e0], i1 = sI[e1], j1 = sJ[e1];
#pragma unroll
        for (int r = 0; r < 7; r++) {
            int c = tx + 32 * r;
            float wlo, whi; funpack2(acc2[ep][r], wlo, whi);
            float s0 = wlo * g_q[i0 * 224 + c] * g_k[j0 * 224 + c];
            float s1 = whi * g_q[i1 * 224 + c] * g_k[j1 * 224 + c];
#pragma unroll
            for (int off = 16; off; off >>= 1) {
                s0 += __shfl_xor_sync(0xffffffffu, s0, off);
                s1 += __shfl_xor_sync(0xffffffffu, s1, off);
            }
            if (tx == 0) {
                sm[OFF_ALPH + e0 * 7 + r] = s0 * sm[OFF_CUT + e0];
                sm[OFF_ALPH + e1 * 7 + r] = s1 * sm[OFF_CUT + e1];
            }
        }
    }
    __syncthreads();

    // ---- Phase C: segment scatter (idx_i sorted)
    if (tid < 224) {
        int h = tid / 56;
        int cur = sI[0]; float acc = 0.f;
#pragma unroll 4
        for (int e = 0; e < vend; e++) {
            int i = sI[e];
            if (i != cur) { atomicAdd(&outx[cur * 224 + tid], acc); acc = 0.f; cur = i; }
            acc += sm[OFF_ALPH + e * 7 + h] * g_v[sJ[e] * 224 + tid];
        }
        atomicAdd(&outx[cur * 224 + tid], acc);
    } else if (tid < 239) {
        int o = tid - 224;
        int dh = (o < 3) ? 4 : ((o < 8) ? 5 : 6);
        int cur = sI[0]; float acc = 0.f;
#pragma unroll 4
        for (int e = 0; e < vend; e++) {
            int i = sI[e];
            if (i != cur) { atomicAdd(&outev[cur * 15 + o], acc); acc = 0.f; cur = i; }
            acc += sm[OFF_ALPH + e * 7 + dh] * ylm[(p0 + e) * 15 + o];
        }
        atomicAdd(&outev[cur * 15 + o], acc);
    }
}

// ---------------------------------------------------------------------------
extern "C" void kernel_launch(void* const* d_in, const int* in_sizes, int n_in,
                              void* d_out, int out_size) {
    const float* x    = (const float*)d_in[0];
    const float* ev   = (const float*)d_in[1];
    const float* rbf  = (const float*)d_in[2];
    const float* ylm  = (const float*)d_in[3];
    const float* cut  = (const float*)d_in[4];
    const int*   idx_i = (const int*)d_in[5];
    const int*   idx_j = (const int*)d_in[6];
    const float* W1r = (const float*)d_in[7];
    const float* b1r = (const float*)d_in[8];
    const float* W2r = (const float*)d_in[9];
    const float* b2r = (const float*)d_in[10];
    const float* W1s = (const float*)d_in[11];
    const float* b1s = (const float*)d_in[12];
    const float* W2s = (const float*)d_in[13];
    const float* b2s = (const float*)d_in[14];
    const float* Wq  = (const float*)d_in[15];
    const float* Wk  = (const float*)d_in[16];
    const float* Wv  = (const float*)d_in[17];

    int N = in_sizes[0] / 224;
    int P = in_sizes[4];
    float* outx  = (float*)d_out;
    float* outev = outx + (size_t)N * 224;

    const int EDGE_SMEM = EDGE_SMEM_FLOATS * 4;  // 74496 B
    cudaFuncSetAttribute(k_edge, cudaFuncAttributeMaxDynamicSharedMemorySize, EDGE_SMEM);

    k_prep<<<512, 256>>>(W2r, W2s, Wq, Wk, Wv, outx, outev, N);
    k_node<<<(N + BN - 1) / BN, 256>>>(x, N);
    k_edge<<<(P + TILE - 1) / TILE, 256, EDGE_SMEM>>>(
        ev, rbf, ylm, cut, idx_i, idx_j,
        W1r, b1r, b2r, W1s, b1s, b2s, outx, outev, P);
}